// round 8
// baseline (speedup 1.0000x reference)
#include <cuda_runtime.h>
#include <cstdint>

// Kuramoto oscillators: B=32, N=2048, K=8, T=20.
// R8: batch-pipelined clusters. 16 clusters x 4 CTAs (grid=64), 512 thr/CTA.
// Each cluster owns TWO batch elements; per step a CTA computes batch0's 512
// oscillators, pushes its 2KB slice to the 3 peers (cp.async.bulk,
// complete_tx on the peers' per-batch-per-buffer mbarrier), then computes
// batch1 and pushes it. The DSMEM round-trip for one batch hides behind the
// other batch's compute. Waits use acquire.CTA scope (canonical TMA-consumer
// pattern: bulk writes land in own smem via the local async proxy).
// Duplicate scatter targets: LAST k wins; n = #distinct nonzero targets.
// eps/n folded into the weights (eps=1, anneal=0).

#define Nn 2048
#define Kk 8
#define Bb 32
#define Tt 20
#define CSZ 4
#define THREADS 512
#define JB 2                                   // batches per cluster
#define NPC (Nn / CSZ)                         // 512 oscillators per CTA
#define SLICE_BYTES (NPC * 4)                  // 2048 bytes per push
#define EXPECT_BYTES ((CSZ - 1) * SLICE_BYTES) // 6144 remote bytes per step

#define TWO_PI     6.28318530717958647692f
#define INV_TWO_PI 0.15915494309189533577f

__device__ __forceinline__ uint32_t smem_u32(const void* p) {
    uint32_t a;
    asm("{ .reg .u64 t; cvta.to.shared.u64 t, %1; cvt.u32.u64 %0, t; }"
        : "=r"(a) : "l"(p));
    return a;
}

__device__ __forceinline__ uint32_t mapa_u32(uint32_t laddr, uint32_t rank) {
    uint32_t r;
    asm("mapa.shared::cluster.u32 %0, %1, %2;" : "=r"(r) : "r"(laddr), "r"(rank));
    return r;
}

__device__ __forceinline__ void mbar_init(uint32_t laddr, uint32_t count) {
    asm volatile("mbarrier.init.shared.b64 [%0], %1;" :: "r"(laddr), "r"(count) : "memory");
}

__device__ __forceinline__ void mbar_arrive_expect_tx(uint32_t laddr, uint32_t tx) {
    asm volatile("mbarrier.arrive.expect_tx.shared.b64 _, [%0], %1;"
                 :: "r"(laddr), "r"(tx) : "memory");
}

__device__ __forceinline__ void bulk_s2s_cluster(uint32_t dst_cluster,
                                                 uint32_t src_cta,
                                                 uint32_t bytes,
                                                 uint32_t rmbar_cluster) {
    asm volatile(
        "cp.async.bulk.shared::cluster.shared::cta.mbarrier::complete_tx::bytes "
        "[%0], [%1], %2, [%3];"
        :: "r"(dst_cluster), "r"(src_cta), "r"(bytes), "r"(rmbar_cluster)
        : "memory");
}

// CTA-scope acquire wait (canonical TMA-consumer pattern; cheaper than cluster)
__device__ __forceinline__ void mbar_wait(uint32_t laddr, uint32_t parity) {
    uint32_t done;
    asm volatile(
        "{ .reg .pred p;\n"
        "  mbarrier.try_wait.parity.acquire.cta.shared::cta.b64 p, [%1], %2;\n"
        "  selp.b32 %0, 1, 0, p; }"
        : "=r"(done) : "r"(laddr), "r"(parity) : "memory");
    if (!done) {
        asm volatile(
            "{ .reg .pred p;\n"
            "WL_%=:\n"
            "  mbarrier.try_wait.parity.acquire.cta.shared::cta.b64 p, [%0], %1, 0x989680;\n"
            "  @p bra.uni WD_%=;\n"
            "  bra.uni WL_%=;\n"
            "WD_%=: }"
            :: "r"(laddr), "r"(parity) : "memory");
    }
}

__global__ void __launch_bounds__(THREADS, 1) __cluster_dims__(CSZ, 1, 1)
osc_kernel(const float* __restrict__ coupling,   // [B,N,K]
           const float* __restrict__ phase0,     // [B,N]
           const float* __restrict__ omega,      // [B,N]
           const int*   __restrict__ conn,       // [N,K]
           float*       __restrict__ out)        // [T+1,B,N]
{
    __shared__ __align__(16) float th[JB][2][Nn];            // phases per batch/buf
    __shared__ __align__(8)  unsigned long long mbar[JB][2];

    uint32_t rank;
    asm("mov.u32 %0, %%cluster_ctarank;" : "=r"(rank));
    const int cid = blockIdx.x / CSZ;          // cluster id: 0..15
    const int tid = threadIdx.x;
    const int n   = (int)rank * NPC + tid;

    uint32_t mb_l[JB][2];
    #pragma unroll
    for (int j = 0; j < JB; ++j) {
        mb_l[j][0] = smem_u32(&mbar[j][0]);
        mb_l[j][1] = smem_u32(&mbar[j][1]);
        if (tid == 0) { mbar_init(mb_l[j][0], 1); mbar_init(mb_l[j][1], 1); }
    }

    // ---- prologue: shared connectivity dedup mask, per-batch weights ----
    int idx[Kk];
    bool win[Kk];
    #pragma unroll
    for (int k = 0; k < Kk; ++k) idx[k] = conn[n * Kk + k];
    #pragma unroll
    for (int k = 0; k < Kk; ++k) {
        bool v = true;
        #pragma unroll
        for (int k2 = k + 1; k2 < Kk; ++k2) v = v && (idx[k2] != idx[k]);
        win[k] = v;
    }

    float w[JB][Kk];
    float p[JB], om[JB];
    #pragma unroll
    for (int j = 0; j < JB; ++j) {
        const int bj = cid * JB + j;
        int cnt = 0;
        #pragma unroll
        for (int k = 0; k < Kk; ++k) {
            const float c = coupling[((size_t)bj * Nn + n) * Kk + k];
            w[j][k] = win[k] ? c : 0.0f;
            cnt += (win[k] && (c != 0.0f)) ? 1 : 0;
        }
        const float inv = (cnt > 0) ? (1.0f / (float)cnt) : 0.0f;
        #pragma unroll
        for (int k = 0; k < Kk; ++k) w[j][k] *= inv;

        p[j]  = phase0[(size_t)bj * Nn + n];
        om[j] = omega[(size_t)bj * Nn + n];
        out[(size_t)bj * Nn + n] = p[j];       // t=0 slice

        // fill full local th[j][0] from gmem (4 per thread)
        #pragma unroll
        for (int q = 0; q < CSZ; ++q) {
            const int m = tid + q * THREADS;
            const float ph = phase0[(size_t)bj * Nn + m];
            th[j][0][m] = ph - TWO_PI * rintf(ph * INV_TWO_PI);
        }
    }
    float pr[JB];
    #pragma unroll
    for (int j = 0; j < JB; ++j)
        pr[j] = p[j] - TWO_PI * rintf(p[j] * INV_TWO_PI);

    // hoisted push addresses (pushing threads tid<3): peer slice dst + peer mbar
    const uint32_t peer = (tid < CSZ - 1)
        ? ((uint32_t)tid < rank ? (uint32_t)tid : (uint32_t)(tid + 1)) : 0u;
    uint32_t src_l[JB][2], dst_r[JB][2], mbr_r[JB][2];
    #pragma unroll
    for (int j = 0; j < JB; ++j) {
        src_l[j][0] = smem_u32(&th[j][0][rank * NPC]);
        src_l[j][1] = smem_u32(&th[j][1][rank * NPC]);
        if (tid < CSZ - 1) {
            dst_r[j][0] = mapa_u32(src_l[j][0], peer);
            dst_r[j][1] = mapa_u32(src_l[j][1], peer);
            mbr_r[j][0] = mapa_u32(mb_l[j][0], peer);
            mbr_r[j][1] = mapa_u32(mb_l[j][1], peer);
        }
    }

    __syncthreads();   // th[*][0] + mbarrier init complete at CTA scope
    // cluster-wide: all mbarriers initialized before any peer bulk signals
    asm volatile("barrier.cluster.arrive.aligned;" ::: "memory");
    asm volatile("barrier.cluster.wait.aligned;"   ::: "memory");

    uint32_t par[JB][2] = {{0, 0}, {0, 0}};

    // ---- time stepping: batch-pipelined ----
    #pragma unroll 1
    for (int t = 0; t < Tt; ++t) {
        const int c  = t & 1;
        const int nb = c ^ 1;
        const size_t obase = (size_t)(t + 1) * (Bb * Nn);

        #pragma unroll
        for (int j = 0; j < JB; ++j) {
            // wait for this batch's buffer-c data (round-trip hidden behind
            // the other batch's compute)
            if (t > 0) { mbar_wait(mb_l[j][c], par[j][c]); par[j][c] ^= 1u; }
            if (t < Tt - 1 && tid == 0)
                mbar_arrive_expect_tx(mb_l[j][nb], EXPECT_BYTES);

            const float* __restrict__ cur = th[j][c];
            float acc = 0.0f;
            #pragma unroll
            for (int k = 0; k < Kk; ++k)
                acc += w[j][k] * __sinf(cur[idx[k]] - pr[j]);

            p[j] += acc + om[j];
            const float prn = p[j] - TWO_PI * rintf(p[j] * INV_TWO_PI);
            pr[j] = prn;

            th[j][nb][n] = prn;
            out[obase + (size_t)(cid * JB + j) * Nn + n] = p[j];

            if (t < Tt - 1) {
                __syncthreads();     // slice complete before engine reads it
                if (tid < CSZ - 1) {
                    asm volatile("fence.proxy.async.shared::cta;" ::: "memory");
                    bulk_s2s_cluster(dst_r[j][nb], src_l[j][nb],
                                     SLICE_BYTES, mbr_r[j][nb]);
                }
            }
        }
    }
}

extern "C" void kernel_launch(void* const* d_in, const int* in_sizes, int n_in,
                              void* d_out, int out_size)
{
    const float* coupling = (const float*)d_in[0];   // [B,N,K] f32
    const float* phase0   = (const float*)d_in[1];   // [B,N]   f32
    const float* omega    = (const float*)d_in[2];   // [B,N]   f32
    const int*   conn     = (const int*)  d_in[3];   // [N,K]   i32
    float*       out      = (float*)d_out;           // [T+1,B,N] f32

    osc_kernel<<<(Bb / JB) * CSZ, THREADS>>>(coupling, phase0, omega, conn, out);
}